// round 7
// baseline (speedup 1.0000x reference)
#include <cuda_runtime.h>

#define EPSF 1e-6f
#define S 32
#define C 3
#define TILE (S * S)   // 1024

// Precomputed Thomas factorizations, 11 time-indices (j=0..5 x-dir, 6..10 y-dir):
//   g_cf2[(j*C+c)*TILE + i*S + r] = (invd, w)
// c_star = -w, so backward sweep is x_i = d_i + w_i * x_{i+1}.
__device__ float2 g_cf2[11 * C * TILE];

// solve order over the 15 substeps, as j-indices into the table
__constant__ int c_jseq[15] = {0, 6, 1, 1, 7, 2, 2, 8, 3, 3, 9, 4, 4, 10, 5};

// ---------------------------------------------------------------------------
// packed f32x2 helpers (PTX-only; ptxas never auto-fuses)
// ---------------------------------------------------------------------------
__device__ __forceinline__ float2 fma2(float2 a, float2 b, float2 c) {
    unsigned long long au = *reinterpret_cast<unsigned long long*>(&a);
    unsigned long long bu = *reinterpret_cast<unsigned long long*>(&b);
    unsigned long long cu = *reinterpret_cast<unsigned long long*>(&c);
    unsigned long long du;
    asm("fma.rn.f32x2 %0, %1, %2, %3;" : "=l"(du) : "l"(au), "l"(bu), "l"(cu));
    return *reinterpret_cast<float2*>(&du);
}
__device__ __forceinline__ float2 mul2(float2 a, float2 b) {
    unsigned long long au = *reinterpret_cast<unsigned long long*>(&a);
    unsigned long long bu = *reinterpret_cast<unsigned long long*>(&b);
    unsigned long long du;
    asm("mul.rn.f32x2 %0, %1, %2;" : "=l"(du) : "l"(au), "l"(bu));
    return *reinterpret_cast<float2*>(&du);
}

// ---------------------------------------------------------------------------
// Precompute kernel: one thread per (timeIdx, c, row). 11*3*32 = 1056 threads.
// ---------------------------------------------------------------------------
__global__ void precompute_kernel(const float* __restrict__ ab,
                                  const float* __restrict__ bb,
                                  const float* __restrict__ atc,
                                  const float* __restrict__ btc) {
    int tid = blockIdx.x * blockDim.x + threadIdx.x;
    if (tid >= 11 * C * S) return;
    int j   = tid / (C * S);
    int rem = tid % (C * S);
    int c   = rem / S;
    int r   = rem % S;

    float t, fac;
    const float* bp;
    const float* tp;
    int stride;
    if (j < 6) {                       // x-direction, t = j*DT, dt = DT/2
        t   = (float)(j * 0.1);
        fac = 0.05f;
        bp  = ab + (c * S + r) * S;
        tp  = atc + (c * S + r) * S;
        stride = 1;
    } else {                           // y-direction, t = DT/2 + jy*DT, dt = DT
        int jy = j - 6;
        t   = (float)(0.05 + jy * 0.1);
        fac = 0.1f;
        bp  = bb + c * TILE + r;
        tp  = btc + c * TILE + r;
        stride = S;
    }
    float2* out2 = g_cf2 + (j * C + c) * TILE;

    float coef[S];
#pragma unroll
    for (int i = 0; i < S; ++i)
        coef[i] = fmaxf(bp[i * stride] + t * tp[i * stride], EPSF);

    float cs[S];
    cs[0] = (coef[0] + coef[0] + coef[1]) / 3.0f * fac;
#pragma unroll
    for (int i = 1; i < S - 1; ++i)
        cs[i] = (coef[i - 1] + coef[i] + coef[i + 1]) / 3.0f * fac;
    cs[S - 1] = (coef[S - 2] + coef[S - 1] + coef[S - 1]) / 3.0f * fac;

    float wprev = 0.0f;
#pragma unroll
    for (int i = 0; i < S; ++i) {
        float b = 1.0f + 2.0f * cs[i];
        if (i == 0)     b = 1.0f + cs[0];
        if (i == S - 1) b = 1.0f + cs[S - 1];
        float denom = b - cs[i] * wprev + EPSF;
        float invd  = 1.0f / denom;
        float w     = cs[i] * invd;
        out2[i * S + r] = make_float2(invd, w);
        wprev = w;
    }
}

// ---------------------------------------------------------------------------
// Main fused ADI kernel: ONE warp per CTA, K=4 tiles as TWO f32x2 pairs.
// v0[i]=(tileA,tileB), v1[i]=(tileC,tileD) at (row=lane, pos=i).
// One coefficient stream + one warr[] feeds both pairs -> two independent
// 4-cycle FMA chains per thread (the ILP that made R2 fastest), no reloads.
// ---------------------------------------------------------------------------
__global__ __launch_bounds__(32, 10)
void adi_kernel(const float* __restrict__ uin, float* __restrict__ uout) {
    __shared__ float2 s0[S * 33];   // pair-0 slab (padded, conflict-free)
    __shared__ float2 s1[S * 33];   // pair-1 slab

    const int lane = threadIdx.x;
    const int cid  = blockIdx.x % C;
    const int bg   = blockIdx.x / C;                    // 0..511 batch-quad
    const int base0 = (4 * bg) * C * TILE + cid * TILE; // tile k at +k*C*TILE

    float2 v0[S], v1[S];
    float  warr[S];

    // ---- load: gmem (coalesced) -> slabs (interleaved comps) -> regs ----
    {
        float* f0 = reinterpret_cast<float*>(s0);
        float* f1 = reinterpret_cast<float*>(s1);
#pragma unroll
        for (int r = 0; r < S; ++r) {
            f0[2 * (r * 33 + lane) + 0] = uin[base0 + 0 * C * TILE + r * S + lane];
            f0[2 * (r * 33 + lane) + 1] = uin[base0 + 1 * C * TILE + r * S + lane];
            f1[2 * (r * 33 + lane) + 0] = uin[base0 + 2 * C * TILE + r * S + lane];
            f1[2 * (r * 33 + lane) + 1] = uin[base0 + 3 * C * TILE + r * S + lane];
        }
        __syncwarp();
#pragma unroll
        for (int i = 0; i < S; ++i) {
            v0[i] = s0[lane * 33 + i];
            v1[i] = s1[lane * 33 + i];
        }
        __syncwarp();
    }

    // ---- Thomas solve: shared coeff stream, two independent chains ----
    auto solve = [&](int j) {
        const float2* __restrict__ cf2 = g_cf2 + (j * C + cid) * TILE;
        float2 cb[2][4];
#pragma unroll
        for (int m = 0; m < 4; ++m)
            cb[0][m] = __ldg(&cf2[m * S + lane]);
        float2 dp0 = make_float2(0.0f, 0.0f);
        float2 dp1 = make_float2(0.0f, 0.0f);
#pragma unroll
        for (int blk = 0; blk < 8; ++blk) {
            if (blk < 7) {
#pragma unroll
                for (int m = 0; m < 4; ++m)
                    cb[(blk + 1) & 1][m] = __ldg(&cf2[((blk + 1) * 4 + m) * S + lane]);
            }
#pragma unroll
            for (int m = 0; m < 4; ++m) {
                const int i = blk * 4 + m;
                float2 iw = cb[blk & 1][m];
                warr[i] = iw.y;
                float2 inv2 = make_float2(iw.x, iw.x);
                float2 w2   = make_float2(iw.y, iw.y);
                float2 t0 = mul2(v0[i], inv2);
                float2 t1 = mul2(v1[i], inv2);
                t0 = fma2(w2, dp0, t0);
                t1 = fma2(w2, dp1, t1);
                v0[i] = t0; dp0 = t0;
                v1[i] = t1; dp1 = t1;
            }
        }
        // backward sweep: w from registers, two interleaved chains
#pragma unroll
        for (int i = S - 2; i >= 0; --i) {
            float2 w2 = make_float2(warr[i], warr[i]);
            v0[i] = fma2(w2, v0[i + 1], v0[i]);
            v1[i] = fma2(w2, v1[i + 1], v1[i]);
        }
    };

    // ---- 32x32 transpose of both pairs via private padded slabs ----
    auto transpose = [&]() {
        __syncwarp();
#pragma unroll
        for (int i = 0; i < S; ++i) {
            s0[lane * 33 + i] = v0[i];
            s1[lane * 33 + i] = v1[i];
        }
        __syncwarp();
#pragma unroll
        for (int i = 0; i < S; ++i) {
            v0[i] = s0[i * 33 + lane];
            v1[i] = s1[i * 33 + lane];
        }
        __syncwarp();
    };

    // 15 substeps: X0 Y0 X1 X1 Y1 X2 X2 Y2 X3 X3 Y3 X4 X4 Y4 X5
#pragma unroll 1
    for (int s = 0; s < 15; ++s) {
        const int j = c_jseq[s];
        solve(j);
        if (s < 14 && ((j < 6) != (c_jseq[s + 1] < 6)))
            transpose();
    }

    // ---- store: regs -> slabs -> gmem (coalesced) ----
    {
        __syncwarp();
#pragma unroll
        for (int i = 0; i < S; ++i) {
            s0[lane * 33 + i] = v0[i];
            s1[lane * 33 + i] = v1[i];
        }
        __syncwarp();
        float* f0 = reinterpret_cast<float*>(s0);
        float* f1 = reinterpret_cast<float*>(s1);
#pragma unroll
        for (int r = 0; r < S; ++r) {
            uout[base0 + 0 * C * TILE + r * S + lane] = f0[2 * (r * 33 + lane) + 0];
            uout[base0 + 1 * C * TILE + r * S + lane] = f0[2 * (r * 33 + lane) + 1];
            uout[base0 + 2 * C * TILE + r * S + lane] = f1[2 * (r * 33 + lane) + 0];
            uout[base0 + 3 * C * TILE + r * S + lane] = f1[2 * (r * 33 + lane) + 1];
        }
    }
}

// ---------------------------------------------------------------------------
extern "C" void kernel_launch(void* const* d_in, const int* in_sizes, int n_in,
                              void* d_out, int out_size) {
    const float* u   = (const float*)d_in[0];
    const float* ab  = (const float*)d_in[1];
    const float* bb  = (const float*)d_in[2];
    const float* atc = (const float*)d_in[3];
    const float* btc = (const float*)d_in[4];
    float* out = (float*)d_out;

    const int B = in_sizes[0] / (C * TILE);   // 2048

    precompute_kernel<<<(11 * C * S + 127) / 128, 128>>>(ab, bb, atc, btc);

    const int nquads = B / 4;                 // 512
    adi_kernel<<<nquads * C, 32>>>(u, out);   // 1536 one-warp CTAs
}

// round 8
// speedup vs baseline: 1.8109x; 1.8109x over previous
#include <cuda_runtime.h>

#define EPSF 1e-6f
#define S 32
#define C 3
#define TILE (S * S)   // 1024

// Precomputed Thomas factorizations, 11 time-indices (j=0..5 x-dir, 6..10 y-dir):
//   g_cf2[(j*C+c)*TILE + i*S + r] = (invd, w)
// c_star = -w, so backward sweep is x_i = d_i + w_i * x_{i+1}.
__device__ float2 g_cf2[11 * C * TILE];

// solve order over the 15 substeps, as j-indices into the table
__constant__ int c_jseq[15] = {0, 6, 1, 1, 7, 2, 2, 8, 3, 3, 9, 4, 4, 10, 5};

// ---------------------------------------------------------------------------
// packed f32x2 helpers (PTX-only; ptxas never auto-fuses)
// ---------------------------------------------------------------------------
__device__ __forceinline__ float2 fma2(float2 a, float2 b, float2 c) {
    unsigned long long au = *reinterpret_cast<unsigned long long*>(&a);
    unsigned long long bu = *reinterpret_cast<unsigned long long*>(&b);
    unsigned long long cu = *reinterpret_cast<unsigned long long*>(&c);
    unsigned long long du;
    asm("fma.rn.f32x2 %0, %1, %2, %3;" : "=l"(du) : "l"(au), "l"(bu), "l"(cu));
    return *reinterpret_cast<float2*>(&du);
}
__device__ __forceinline__ float2 mul2(float2 a, float2 b) {
    unsigned long long au = *reinterpret_cast<unsigned long long*>(&a);
    unsigned long long bu = *reinterpret_cast<unsigned long long*>(&b);
    unsigned long long du;
    asm("mul.rn.f32x2 %0, %1, %2;" : "=l"(du) : "l"(au), "l"(bu));
    return *reinterpret_cast<float2*>(&du);
}

// ---------------------------------------------------------------------------
// Precompute kernel: one thread per (timeIdx, c, row). 11*3*32 = 1056 threads.
// ---------------------------------------------------------------------------
__global__ void precompute_kernel(const float* __restrict__ ab,
                                  const float* __restrict__ bb,
                                  const float* __restrict__ atc,
                                  const float* __restrict__ btc) {
    int tid = blockIdx.x * blockDim.x + threadIdx.x;
    if (tid >= 11 * C * S) return;
    int j   = tid / (C * S);
    int rem = tid % (C * S);
    int c   = rem / S;
    int r   = rem % S;

    float t, fac;
    const float* bp;
    const float* tp;
    int stride;
    if (j < 6) {                       // x-direction, t = j*DT, dt = DT/2
        t   = (float)(j * 0.1);
        fac = 0.05f;
        bp  = ab + (c * S + r) * S;
        tp  = atc + (c * S + r) * S;
        stride = 1;
    } else {                           // y-direction, t = DT/2 + jy*DT, dt = DT
        int jy = j - 6;
        t   = (float)(0.05 + jy * 0.1);
        fac = 0.1f;
        bp  = bb + c * TILE + r;
        tp  = btc + c * TILE + r;
        stride = S;
    }
    float2* out2 = g_cf2 + (j * C + c) * TILE;

    float coef[S];
#pragma unroll
    for (int i = 0; i < S; ++i)
        coef[i] = fmaxf(bp[i * stride] + t * tp[i * stride], EPSF);

    float cs[S];
    cs[0] = (coef[0] + coef[0] + coef[1]) / 3.0f * fac;
#pragma unroll
    for (int i = 1; i < S - 1; ++i)
        cs[i] = (coef[i - 1] + coef[i] + coef[i + 1]) / 3.0f * fac;
    cs[S - 1] = (coef[S - 2] + coef[S - 1] + coef[S - 1]) / 3.0f * fac;

    float wprev = 0.0f;
#pragma unroll
    for (int i = 0; i < S; ++i) {
        float b = 1.0f + 2.0f * cs[i];
        if (i == 0)     b = 1.0f + cs[0];
        if (i == S - 1) b = 1.0f + cs[S - 1];
        float denom = b - cs[i] * wprev + EPSF;
        float invd  = 1.0f / denom;
        float w     = cs[i] * invd;
        out2[i * S + r] = make_float2(invd, w);
        wprev = w;
    }
}

// ---------------------------------------------------------------------------
// Main fused ADI kernel: ONE warp per CTA, K=4 tiles as TWO f32x2 pairs.
// Direct coalesced LDG/STG (column layout) + 12 smem transposes.
// One 8.4KB slab per CTA keeps L1D carveout large for the coefficient tables.
// ---------------------------------------------------------------------------
__global__ __launch_bounds__(32, 8)
void adi_kernel(const float* __restrict__ uin, float* __restrict__ uout) {
    __shared__ float2 sm[S * 33];

    const int lane = threadIdx.x;
    const int cid  = blockIdx.x % C;
    const int bg   = blockIdx.x / C;                    // 0..511 batch-quad
    const int base0 = (4 * bg) * C * TILE + cid * TILE; // tile k at +k*C*TILE

    float2 v0[S], v1[S];   // pair0 = tiles (0,1), pair1 = tiles (2,3)
    float  warr[S];

    // ---- load: direct coalesced LDG, column layout v[i] = u[row i][col lane]
#pragma unroll
    for (int i = 0; i < S; ++i) {
        v0[i].x = uin[base0 + 0 * C * TILE + i * S + lane];
        v0[i].y = uin[base0 + 1 * C * TILE + i * S + lane];
        v1[i].x = uin[base0 + 2 * C * TILE + i * S + lane];
        v1[i].y = uin[base0 + 3 * C * TILE + i * S + lane];
    }

    // ---- 32x32 transpose of both pairs through one padded slab ----
    auto transpose = [&]() {
        __syncwarp();
#pragma unroll
        for (int i = 0; i < S; ++i) sm[lane * 33 + i] = v0[i];
        __syncwarp();
#pragma unroll
        for (int i = 0; i < S; ++i) v0[i] = sm[i * 33 + lane];
        __syncwarp();
#pragma unroll
        for (int i = 0; i < S; ++i) sm[lane * 33 + i] = v1[i];
        __syncwarp();
#pragma unroll
        for (int i = 0; i < S; ++i) v1[i] = sm[i * 33 + lane];
        __syncwarp();
    };

    // ---- Thomas solve: shared coeff stream, two independent f32x2 chains ----
    auto solve = [&](int j) {
        const float2* __restrict__ cf2 = g_cf2 + (j * C + cid) * TILE;
        float2 cb[2][4];
#pragma unroll
        for (int m = 0; m < 4; ++m)
            cb[0][m] = __ldg(&cf2[m * S + lane]);
        float2 dp0 = make_float2(0.0f, 0.0f);
        float2 dp1 = make_float2(0.0f, 0.0f);
#pragma unroll
        for (int blk = 0; blk < 8; ++blk) {
            if (blk < 7) {
#pragma unroll
                for (int m = 0; m < 4; ++m)
                    cb[(blk + 1) & 1][m] = __ldg(&cf2[((blk + 1) * 4 + m) * S + lane]);
            }
#pragma unroll
            for (int m = 0; m < 4; ++m) {
                const int i = blk * 4 + m;
                float2 iw = cb[blk & 1][m];
                warr[i] = iw.y;
                float2 inv2 = make_float2(iw.x, iw.x);
                float2 w2   = make_float2(iw.y, iw.y);
                float2 t0 = mul2(v0[i], inv2);
                float2 t1 = mul2(v1[i], inv2);
                t0 = fma2(w2, dp0, t0);
                t1 = fma2(w2, dp1, t1);
                v0[i] = t0; dp0 = t0;
                v1[i] = t1; dp1 = t1;
            }
        }
        // backward sweep: w from registers, two interleaved chains
#pragma unroll
        for (int i = S - 2; i >= 0; --i) {
            float2 w2 = make_float2(warr[i], warr[i]);
            v0[i] = fma2(w2, v0[i + 1], v0[i]);
            v1[i] = fma2(w2, v1[i + 1], v1[i]);
        }
    };

    // loaded column layout -> transpose to row layout for first X solve
    transpose();

    // 15 substeps: X0 Y0 X1 X1 Y1 X2 X2 Y2 X3 X3 Y3 X4 X4 Y4 X5
#pragma unroll 1
    for (int s = 0; s < 15; ++s) {
        const int j = c_jseq[s];
        solve(j);
        if (s < 14 && ((j < 6) != (c_jseq[s + 1] < 6)))
            transpose();
    }

    // row layout -> column layout, then direct coalesced STG
    transpose();
#pragma unroll
    for (int i = 0; i < S; ++i) {
        uout[base0 + 0 * C * TILE + i * S + lane] = v0[i].x;
        uout[base0 + 1 * C * TILE + i * S + lane] = v0[i].y;
        uout[base0 + 2 * C * TILE + i * S + lane] = v1[i].x;
        uout[base0 + 3 * C * TILE + i * S + lane] = v1[i].y;
    }
}

// ---------------------------------------------------------------------------
extern "C" void kernel_launch(void* const* d_in, const int* in_sizes, int n_in,
                              void* d_out, int out_size) {
    const float* u   = (const float*)d_in[0];
    const float* ab  = (const float*)d_in[1];
    const float* bb  = (const float*)d_in[2];
    const float* atc = (const float*)d_in[3];
    const float* btc = (const float*)d_in[4];
    float* out = (float*)d_out;

    const int B = in_sizes[0] / (C * TILE);   // 2048

    precompute_kernel<<<(11 * C * S + 127) / 128, 128>>>(ab, bb, atc, btc);

    const int nquads = B / 4;                 // 512
    adi_kernel<<<nquads * C, 32>>>(u, out);   // 1536 one-warp CTAs
}